// round 17
// baseline (speedup 1.0000x reference)
#include <cuda_runtime.h>
#include <cstdint>

#define VOCAB 50257
#define DIM   2048
#define RNK   64
#define MT    64             // tokens per CTA
#define CCOLS 64             // d-columns per chunk
#define NCHUNK (DIM / CCOLS) // 32
#define NTHREADS 256
#define BSTRIDE 68           // bounce row stride (floats)

// B pre-transposed into per-(chunk64, ng, s, nt) fragment layout (512 KB)
__device__ float g_Bfrag[DIM * RNK];

__device__ __forceinline__ uint32_t smem_u32(const void* p) {
    uint32_t a;
    asm("{ .reg .u64 t; cvta.to.shared.u64 t, %1; cvt.u32.u64 %0, t; }" : "=r"(a) : "l"(p));
    return a;
}
__device__ __forceinline__ uint32_t to_tf32(float v) {
    uint32_t r;
    asm("cvt.rna.tf32.f32 %0, %1;" : "=r"(r) : "f"(v));
    return r;
}
__device__ __forceinline__ void cpa16(uint32_t dst, const void* src) {
    asm volatile("cp.async.cg.shared.global [%0], [%1], 16;" :: "r"(dst), "l"(src));
}
__device__ __forceinline__ void pf_l2(const void* p) {
    asm volatile("prefetch.global.L2 [%0];" :: "l"(p));
}
__device__ __forceinline__ void mma_tf32(float* d, const float4& a, const float2& b) {
    asm volatile(
        "mma.sync.aligned.m16n8k8.row.col.f32.tf32.tf32.f32 "
        "{%0,%1,%2,%3}, {%4,%5,%6,%7}, {%8,%9}, {%0,%1,%2,%3};"
        : "+f"(d[0]), "+f"(d[1]), "+f"(d[2]), "+f"(d[3])
        : "r"(__float_as_uint(a.x)), "r"(__float_as_uint(a.y)),
          "r"(__float_as_uint(a.z)), "r"(__float_as_uint(a.w)),
          "r"(__float_as_uint(b.x)), "r"(__float_as_uint(b.y)));
}
__device__ __forceinline__ void stcs2(float* p, float2 v) {
    asm volatile("st.global.cs.v2.f32 [%0], {%1, %2};" :: "l"(p), "f"(v.x), "f"(v.y));
}

// ---- prep: Bm[d][r] -> tf32 fragments grouped per (chunk64, ng, s, nt) ----
// float2 slot: (((c*4+ng)*8+s)*2+nt)*32 + lane ; lane = n8*4+(kq&3), reg = kq>>2
__global__ void prep_B(const float* __restrict__ Bm) {
    int idx = blockIdx.x * blockDim.x + threadIdx.x;   // 0..131071
    int d = idx >> 6, r = idx & 63;
    uint32_t tv = to_tf32(Bm[idx]);
    int c = d >> 6, colin = d & 63;
    int ng = colin >> 4, n16 = colin & 15;
    int nt = n16 >> 3, n8 = n16 & 7;
    int s = r >> 3, kq = r & 7;
    int lane = n8 * 4 + (kq & 3), reg = kq >> 2;
    int f2 = (((c * 4 + ng) * 8 + s) * 2 + nt) * 32 + lane;
    g_Bfrag[f2 * 2 + reg] = __uint_as_float(tv);
}

// ---- main: one CTA per 64-token tile (256 CTAs); cross-chunk software pipeline ----
__global__ void __launch_bounds__(NTHREADS, 2)
lora_main(const int* __restrict__ x,
          const float* __restrict__ W,
          const float* __restrict__ A,
          float* __restrict__ out) {
    extern __shared__ float sm[];
    float* As     = sm;                    // 4096 floats (16 KB): A staging
    float* Bs     = sm + 4096;             // 2 x 4096 floats (32 KB): B ping-pong
    float* bounce = sm + 4096 + 8192;      // 2 x 64*68 = 8704 floats (34 KB)
    int*   toks   = (int*)(sm + 4096 + 8192 + 8704);

    const int tid   = threadIdx.x;
    const int tBase = blockIdx.x * MT;

    if (tid < MT) toks[tid] = x[tBase + tid];

    // prologue: prefetch B chunk 0 (16 KB)
    {
        uint32_t dst = smem_u32(Bs);
        #pragma unroll
        for (int j = 0; j < 4; ++j) {
            int i4 = j * NTHREADS + tid;
            cpa16(dst + i4 * 16, g_Bfrag + i4 * 4);
        }
        asm volatile("cp.async.commit_group;");
    }
    __syncthreads();   // toks visible

    // gather A into fragment layout (validated R14 mapping)
    #pragma unroll 4
    for (int i = tid; i < MT * RNK; i += NTHREADS) {
        int t = i & (MT - 1);
        int r = i >> 6;
        uint32_t tv = to_tf32(__ldg(A + (size_t)r * VOCAB + toks[t]));
        int s = r >> 3, kq = r & 7;
        int mtile = t >> 4, row16 = t & 15;
        int grp = row16 & 7, hi = row16 >> 3;
        int lane = grp * 4 + (kq & 3);
        int reg = (kq >> 2) * 2 + hi;
        As[((s * 4 + mtile) * 32 + lane) * 4 + reg] = __uint_as_float(tv);
    }
    __syncthreads();   // A staging complete

    const int wid  = tid >> 5;
    const int lane = tid & 31;
    const int mg   = wid >> 2;        // 0..1 : 32-token half (MMA)
    const int ng   = wid & 3;         // 0..3 : 16-col group  (MMA)
    const int grp  = lane >> 2;
    const int tig  = lane & 3;

    // hoist this warp's A slice into registers ONCE (64 regs)
    float4 afrag[8][2];
    #pragma unroll
    for (int s = 0; s < 8; ++s)
        #pragma unroll
        for (int mt = 0; mt < 2; ++mt)
            afrag[s][mt] = *(const float4*)&As[((s * 4 + mg * 2 + mt) * 32 + lane) * 4];

    // epilogue row ownership: warp owns rows {i*8 + wid}, i = 0..7
    int tokE[8];
    #pragma unroll
    for (int i = 0; i < 8; ++i) tokE[i] = toks[i * 8 + wid];

    // W L2-prefetch identity: lanes 0..15 cover 8 rows x 2 cache lines (256B/row slice)
    const float* wPbase = nullptr;
    if (lane < 16) {
        int tokP = toks[(lane >> 1) * 8 + wid];
        wPbase = W + (size_t)tokP * DIM + (lane & 1) * 32;
        pf_l2(wPbase);   // chunk 0
    }

    #pragma unroll 1
    for (int c = 0; c < NCHUNK; ++c) {
        asm volatile("cp.async.wait_group 0;");
        __syncthreads();   // B[c] visible; bounce[c&1] free; bounce[(c-1)&1] full

        if (lane < 16 && c + 1 < NCHUNK) pf_l2(wPbase + (c + 1) * CCOLS);

        // ---- issue W loads for chunk c-1 (latency covered by MMA below) ----
        float2 wv[8];
        if (c > 0) {
            const int colP = (c - 1) * CCOLS + lane * 2;
            #pragma unroll
            for (int i = 0; i < 8; ++i)
                wv[i] = __ldg((const float2*)(W + (size_t)tokE[i] * DIM + colP));
        }

        // ---- MMA: warp tile m32 x n16, K=64; A in regs ----
        const float* curB = Bs + (c & 1) * 4096;
        float acc[2][2][4];
        #pragma unroll
        for (int mt = 0; mt < 2; ++mt)
            #pragma unroll
            for (int j = 0; j < 2; ++j)
                #pragma unroll
                for (int k = 0; k < 4; ++k) acc[mt][j][k] = 0.f;

        #pragma unroll
        for (int s = 0; s < 8; ++s) {
            float2 b[2];
            #pragma unroll
            for (int j = 0; j < 2; ++j)
                b[j] = *(const float2*)&curB[(((ng * 8 + s) * 2 + j) * 32 + lane) * 2];
            #pragma unroll
            for (int mt = 0; mt < 2; ++mt)
                #pragma unroll
                for (int j = 0; j < 2; ++j)
                    mma_tf32(acc[mt][j], afrag[s][mt], b[j]);
        }

        // ---- STS acc -> bounce[c&1] ----
        float* curBo = bounce + (c & 1) * (MT * BSTRIDE);
        #pragma unroll
        for (int mt = 0; mt < 2; ++mt) {
            int row0 = mg * 32 + mt * 16 + grp;
            #pragma unroll
            for (int j = 0; j < 2; ++j) {
                int col = ng * 16 + j * 8 + tig * 2;
                *(float2*)&curBo[row0 * BSTRIDE + col] =
                    make_float2(acc[mt][j][0], acc[mt][j][1]);
                *(float2*)&curBo[(row0 + 8) * BSTRIDE + col] =
                    make_float2(acc[mt][j][2], acc[mt][j][3]);
            }
        }

        // ---- issue B(c+1) cp.async into alternate buffer ----
        if (c + 1 < NCHUNK) {
            const float* src = g_Bfrag + (c + 1) * 4096;
            uint32_t dst = smem_u32(Bs + ((c + 1) & 1) * 4096);
            #pragma unroll
            for (int j = 0; j < 4; ++j) {
                int i4 = j * NTHREADS + tid;
                cpa16(dst + i4 * 16, src + i4 * 4);
            }
            asm volatile("cp.async.commit_group;");
        }

        // ---- epilogue for chunk c-1: smem bounce + landed wv, streaming stores ----
        if (c > 0) {
            const float* pb = bounce + ((c - 1) & 1) * (MT * BSTRIDE);
            const int colP = (c - 1) * CCOLS + lane * 2;
            #pragma unroll
            for (int i = 0; i < 8; ++i) {
                int row = i * 8 + wid;
                float2 l = *(const float2*)&pb[row * BSTRIDE + lane * 2];
                float2 r;
                r.x = fmaf(16.f, l.x, wv[i].x);
                r.y = fmaf(16.f, l.y, wv[i].y);
                stcs2(out + (size_t)(tBase + row) * DIM + colP, r);
            }
        }
    }

    // ---- tail: epilogue for the last chunk ----
    __syncthreads();
    {
        const int cL = NCHUNK - 1;
        const float* pb = bounce + (cL & 1) * (MT * BSTRIDE);
        const int colP = cL * CCOLS + lane * 2;
        #pragma unroll
        for (int i = 0; i < 8; ++i) {
            int row = i * 8 + wid;
            float2 w = __ldg((const float2*)(W + (size_t)tokE[i] * DIM + colP));
            float2 l = *(const float2*)&pb[row * BSTRIDE + lane * 2];
            float2 r;
            r.x = fmaf(16.f, l.x, w.x);
            r.y = fmaf(16.f, l.y, w.y);
            stcs2(out + (size_t)(tBase + row) * DIM + colP, r);
        }
    }
}

extern "C" void kernel_launch(void* const* d_in, const int* in_sizes, int n_in,
                              void* d_out, int out_size) {
    const int*   x  = (const int*)d_in[0];
    const float* W  = (const float*)d_in[1];
    const float* A  = (const float*)d_in[2];
    const float* Bm = (const float*)d_in[3];
    float* out = (float*)d_out;

    const int ntok = in_sizes[0];   // 16384

    const int smemBytes = (4096 + 8192 + 8704) * 4 + MT * 4;   // 84,224 B
    cudaFuncSetAttribute(lora_main,
                         cudaFuncAttributeMaxDynamicSharedMemorySize, smemBytes);

    prep_B<<<(DIM * RNK) / 256, 256>>>(Bm);
    lora_main<<<ntok / MT, NTHREADS, smemBytes>>>(x, W, A, out);
}